// round 2
// baseline (speedup 1.0000x reference)
#include <cuda_runtime.h>
#include <cstdint>

// Problem constants
#define CIN   256
#define CMID  512
#define COUT  256
#define IMGW  56
#define HW    3136      // 56*56
#define BATCH 32
#define KCONV 2304      // 9*256

// Scratch (device globals — allocation-free rule)
__device__ float g_y[BATCH * CMID * HW];   // 205 MB intermediate (fp32)
__device__ float g_wA[KCONV * CMID];       // conv1 weights, [k][m] K-major
__device__ float g_wB[CMID * COUT];        // 1x1 weights, [k][m] K-major (tf32-rounded)

__device__ __forceinline__ uint32_t f2tf32(float f) {
    uint32_t r;
    asm("cvt.rna.tf32.f32 %0, %1;" : "=r"(r) : "f"(f));
    return r;
}

// Reorder binary_w [cm][ci][kh][kw] -> g_wA[(kh*3+kw)*256+ci][cm]
__global__ void prep_wA(const float* __restrict__ bw) {
    int idx = blockIdx.x * blockDim.x + threadIdx.x;
    if (idx >= KCONV * CMID) return;
    int m = idx % CMID;
    int k = idx / CMID;
    int ci = k & 255;
    int r  = k >> 8;
    int kh = r / 3, kw = r % 3;
    g_wA[idx] = bw[((m * CIN + ci) * 3 + kh) * 3 + kw];   // ternary: exact in tf32
}

// Reorder fc_w [co][cm] -> g_wB[cm][co], rounded to tf32
__global__ void prep_wB(const float* __restrict__ fw) {
    int idx = blockIdx.x * blockDim.x + threadIdx.x;
    if (idx >= CMID * COUT) return;
    int m = idx % COUT;
    int k = idx / COUT;
    g_wB[idx] = __uint_as_float(f2tf32(fw[m * CMID + k]));
}

// Tiled TF32 mma.sync GEMM.
// CONV1=true : A=g_wA (512x2304), B=im2col(x) per batch, out=relu -> g_y
// CONV1=false: A=g_wB (256x512),  B=g_y per batch,      out=d_out + bias
template <bool CONV1>
__global__ __launch_bounds__(256)
void gemm_kernel(const float* __restrict__ xin,
                 const float* __restrict__ bias,
                 float* __restrict__ outp)
{
    constexpr int BM = 128, BN = 64, BK = 32;
    constexpr int Ktot = CONV1 ? KCONV : CMID;
    constexpr int Mtot = CONV1 ? CMID : COUT;

    __shared__ float As[BK][BM + 8];   // stride 136 -> frag banks 8c+g (conflict-free)
    __shared__ float Bs[BK][BN + 8];   // stride 72  -> frag banks 8c+g (conflict-free)

    const int b    = blockIdx.z;
    const int m0   = blockIdx.y * BM;
    const int n0   = blockIdx.x * BN;
    const int tid  = threadIdx.x;
    const int lane = tid & 31;
    const int warp = tid >> 5;
    const int wm   = (warp & 3) * 32;   // warp m-offset
    const int wn   = (warp >> 2) * 32;  // warp n-offset

    const float* Aglob = CONV1 ? g_wA : g_wB;
    const float* Bbase = CONV1 ? (xin + b * CIN * HW) : (g_y + b * CMID * HW);

    // B-load coords (fixed per thread across k-loop)
    const int nl  = tid & 63;
    const int kr0 = tid >> 6;         // 0..3
    const int n   = n0 + nl;
    const int hh  = n / IMGW;
    const int ww  = n % IMGW;

    // A-load coords
    const int acol = tid & 127;
    const int akr  = tid >> 7;        // 0..1

    float acc[2][4][4];
    #pragma unroll
    for (int i = 0; i < 2; i++)
        #pragma unroll
        for (int j = 0; j < 4; j++)
            #pragma unroll
            for (int c = 0; c < 4; c++) acc[i][j][c] = 0.f;

    for (int kt = 0; kt < Ktot / BK; ++kt) {
        // ---- load A tile [BK x BM] ----
        {
            const float* src = Aglob + (kt * BK + akr) * Mtot + m0 + acol;
            #pragma unroll
            for (int i = 0; i < BK / 2; ++i)
                As[akr + 2 * i][acol] = src[2 * i * Mtot];
        }
        // ---- load B tile [BK x BN] ----
        if (CONV1) {
            // k = r*256 + ci, BK chunk never crosses r boundary
            const int r   = kt >> 3;
            const int kh  = r / 3, kw = r % 3;
            const int ci0 = (kt & 7) * 32;
            const int ih  = hh + kh - 1;
            const int iw  = ww + kw - 1;
            const bool inb = ((unsigned)ih < (unsigned)IMGW) &&
                             ((unsigned)iw < (unsigned)IMGW);
            const float* src = Bbase + (ci0 + kr0) * HW + ih * IMGW + iw;
            #pragma unroll
            for (int j = 0; j < 8; ++j) {
                float v = inb ? src[4 * j * HW] : 0.f;
                Bs[kr0 + 4 * j][nl] = __uint_as_float(f2tf32(v));
            }
        } else {
            const float* src = Bbase + (kt * BK + kr0) * HW + n;
            #pragma unroll
            for (int j = 0; j < 8; ++j)
                Bs[kr0 + 4 * j][nl] = __uint_as_float(f2tf32(src[4 * j * HW]));
        }
        __syncthreads();

        // ---- compute: 4 k-steps of m16n8k8 ----
        #pragma unroll
        for (int kk = 0; kk < 4; ++kk) {
            const int kc = kk * 8 + (lane & 3);
            const int gr = lane >> 2;
            uint32_t a[2][4], bf[4][2];
            #pragma unroll
            for (int mt = 0; mt < 2; ++mt) {
                const int row = wm + mt * 16 + gr;
                a[mt][0] = __float_as_uint(As[kc][row]);
                a[mt][1] = __float_as_uint(As[kc][row + 8]);
                a[mt][2] = __float_as_uint(As[kc + 4][row]);
                a[mt][3] = __float_as_uint(As[kc + 4][row + 8]);
            }
            #pragma unroll
            for (int nt = 0; nt < 4; ++nt) {
                const int colB = wn + nt * 8 + gr;
                bf[nt][0] = __float_as_uint(Bs[kc][colB]);
                bf[nt][1] = __float_as_uint(Bs[kc + 4][colB]);
            }
            #pragma unroll
            for (int mt = 0; mt < 2; ++mt)
                #pragma unroll
                for (int nt = 0; nt < 4; ++nt)
                    asm volatile(
                        "mma.sync.aligned.m16n8k8.row.col.f32.tf32.tf32.f32 "
                        "{%0,%1,%2,%3}, {%4,%5,%6,%7}, {%8,%9}, {%0,%1,%2,%3};\n"
                        : "+f"(acc[mt][nt][0]), "+f"(acc[mt][nt][1]),
                          "+f"(acc[mt][nt][2]), "+f"(acc[mt][nt][3])
                        : "r"(a[mt][0]), "r"(a[mt][1]),
                          "r"(a[mt][2]), "r"(a[mt][3]),
                          "r"(bf[nt][0]), "r"(bf[nt][1]));
        }
        __syncthreads();
    }

    // ---- epilogue ----
    float* dst = CONV1 ? g_y + b * CMID * HW : outp + b * COUT * HW;
    const int gr = lane >> 2;
    const int gc = (lane & 3) * 2;
    #pragma unroll
    for (int mt = 0; mt < 2; ++mt) {
        #pragma unroll
        for (int nt = 0; nt < 4; ++nt) {
            #pragma unroll
            for (int c = 0; c < 4; ++c) {
                const int row = m0 + wm + mt * 16 + gr + ((c >= 2) ? 8 : 0);
                const int col = n0 + wn + nt * 8 + gc + (c & 1);
                float v = acc[mt][nt][c];
                if (CONV1) {
                    dst[row * HW + col] = fmaxf(v, 0.f);
                } else {
                    dst[row * HW + col] = v + bias[row];
                }
            }
        }
    }
}

extern "C" void kernel_launch(void* const* d_in, const int* in_sizes, int n_in,
                              void* d_out, int out_size) {
    (void)in_sizes; (void)n_in; (void)out_size;
    const float* x  = (const float*)d_in[0];
    const float* bw = (const float*)d_in[1];   // binary_w [512,256,3,3]
    const float* fw = (const float*)d_in[2];   // fc_w [256,512,1,1]
    const float* fb = (const float*)d_in[3];   // fc_b [256]
    float* out = (float*)d_out;

    prep_wA<<<(KCONV * CMID + 255) / 256, 256>>>(bw);
    prep_wB<<<(CMID * COUT + 255) / 256, 256>>>(fw);

    // conv1 + relu -> g_y : M=512 (4 tiles), N=3136 (49 tiles), 32 batches
    gemm_kernel<true><<<dim3(49, 4, 32), 256>>>(x, nullptr, nullptr);
    // 1x1 conv + bias -> out : M=256 (2 tiles)
    gemm_kernel<false><<<dim3(49, 2, 32), 256>>>(nullptr, fb, out);
}

// round 4
// speedup vs baseline: 1.2733x; 1.2733x over previous
#include <cuda_runtime.h>
#include <cstdint>

// Problem constants
#define CIN   256
#define CMID  512
#define COUT  256
#define IMGW  56
#define HW    3136      // 56*56
#define BATCH 32
#define KCONV 2304      // 9*256

// Scratch (device globals — allocation-free rule)
__device__ float g_x [BATCH * CIN  * HW];          // tf32-rounded input (103 MB)
__device__ float g_y [BATCH * CMID * HW + 8192];   // intermediate, tf32-rounded (+pad)
__device__ float g_wA[KCONV * CMID];               // conv1 weights [k][m]
__device__ float g_wB[CMID * COUT];                // 1x1 weights [k][m], tf32-rounded

__device__ __forceinline__ uint32_t f2tf32(float f) {
    uint32_t r;
    asm("cvt.rna.tf32.f32 %0, %1;" : "=r"(r) : "f"(f));
    return r;
}

__device__ __forceinline__ void cp16(uint32_t dst, const float* src) {
    asm volatile("cp.async.cg.shared.global [%0], [%1], 16;\n" :: "r"(dst), "l"(src));
}

// ---------------- prep kernels ----------------
__global__ void prep_wA(const float* __restrict__ bw) {
    int idx = blockIdx.x * blockDim.x + threadIdx.x;
    if (idx >= KCONV * CMID) return;
    int m = idx % CMID;
    int k = idx / CMID;
    int ci = k & 255;
    int r  = k >> 8;
    int kh = r / 3, kw = r % 3;
    g_wA[idx] = bw[((m * CIN + ci) * 3 + kh) * 3 + kw];   // ternary: exact
}

__global__ void prep_wB(const float* __restrict__ fw) {
    int idx = blockIdx.x * blockDim.x + threadIdx.x;
    if (idx >= CMID * COUT) return;
    int m = idx % COUT;
    int k = idx / COUT;
    g_wB[idx] = __uint_as_float(f2tf32(fw[m * CMID + k]));
}

__global__ void prep_x(const float* __restrict__ x) {
    int idx = blockIdx.x * blockDim.x + threadIdx.x;
    if (idx >= BATCH * CIN * HW) return;
    g_x[idx] = __uint_as_float(f2tf32(x[idx]));
}

// ---------------- main GEMM ----------------
// Block tile 128x128, BK=32, 8 warps (2 x 4), warp tile 64x32.
// Double-buffered smem; cp.async for A (and conv2 B); reg-staged LDG im2col for conv1 B.
#define BM 128
#define BN 128
#define BK 32
#define APAD (BM + 8)   // 136 floats
#define STAGEF (BK * 136 * 2)   // As + Bs per stage (floats) = 8704

template <bool CONV1>
__global__ __launch_bounds__(256, 2)
void gemm_kernel(const float* __restrict__ bias, float* __restrict__ outp)
{
    constexpr int Ktot = CONV1 ? KCONV : CMID;
    constexpr int Mtot = CONV1 ? CMID : COUT;
    constexpr int KT   = Ktot / BK;

    extern __shared__ float smem[];   // 2 stages * (As[32][136] + Bs[32][136])

    const int b    = blockIdx.z;
    const int m0   = blockIdx.y * BM;
    const int n0   = blockIdx.x * BN;
    const int tid  = threadIdx.x;
    const int lane = tid & 31;
    const int warp = tid >> 5;
    const int wm   = (warp & 1) * 64;
    const int wn   = (warp >> 1) * 32;

    const float* Aglob = CONV1 ? g_wA : g_wB;
    const float* Bbase = CONV1 ? (g_x + b * CIN * HW) : (g_y + b * CMID * HW);

    // A cp.async coords: 4 chunks of 16B per thread
    const int arow0 = tid >> 5;          // 0..7, +8*i
    const int acol  = (lane) * 4;        // float offset within row

    // conv1 B (im2col) coords
    const int nl  = tid & 127;
    const int kr  = tid >> 7;            // 0..1
    const int n   = n0 + nl;
    const int hh  = n / IMGW;            // may exceed 55 on tail tile -> inb=false
    const int ww  = n % IMGW;

    float stage[16];                      // conv1 B staging regs

    float acc[4][4][4];
    #pragma unroll
    for (int i = 0; i < 4; i++)
        #pragma unroll
        for (int j = 0; j < 4; j++)
            #pragma unroll
            for (int c = 0; c < 4; c++) acc[i][j][c] = 0.f;

    // ---- tile loaders ----
    auto load_A = [&](int kt, float* As) {
        uint32_t dbase = (uint32_t)__cvta_generic_to_shared(As);
        #pragma unroll
        for (int i = 0; i < 4; ++i) {
            int row = arow0 + 8 * i;
            cp16(dbase + (uint32_t)(row * 136 + acol) * 4,
                 Aglob + (kt * BK + row) * Mtot + m0 + acol);
        }
    };
    auto load_B2 = [&](int kt, float* Bs) {   // conv2 only
        uint32_t dbase = (uint32_t)__cvta_generic_to_shared(Bs);
        #pragma unroll
        for (int i = 0; i < 4; ++i) {
            int row = arow0 + 8 * i;
            cp16(dbase + (uint32_t)(row * 136 + acol) * 4,
                 Bbase + (kt * BK + row) * HW + n0 + acol);
        }
    };
    auto ldg_B1 = [&](int kt) {               // conv1 only: im2col gather -> regs
        const int r   = kt >> 3;
        const int kh  = r / 3, kw = r % 3;
        const int ci0 = (kt & 7) * 32;
        const int ih  = hh + kh - 1;
        const int iw  = ww + kw - 1;
        const bool inb = ((unsigned)ih < (unsigned)IMGW) &&
                         ((unsigned)iw < (unsigned)IMGW);
        const float* src = Bbase + (ci0 + kr) * HW + ih * IMGW + iw;
        #pragma unroll
        for (int j = 0; j < 16; ++j)
            stage[j] = inb ? __ldg(src + 2 * j * HW) : 0.f;
    };
    auto sts_B1 = [&](float* Bs) {
        #pragma unroll
        for (int j = 0; j < 16; ++j)
            Bs[(kr + 2 * j) * 136 + nl] = stage[j];
    };

    // ---- compute on one stage ----
    auto compute = [&](const float* As, const float* Bs) {
        const int gr = lane >> 2;
        const int kb = lane & 3;
        #pragma unroll
        for (int kk = 0; kk < 4; ++kk) {
            const int kc = kk * 8 + kb;
            uint32_t a[4][4], bf[4][2];
            #pragma unroll
            for (int mt = 0; mt < 4; ++mt) {
                const int row = wm + mt * 16 + gr;
                a[mt][0] = __float_as_uint(As[kc * 136 + row]);
                a[mt][1] = __float_as_uint(As[kc * 136 + row + 8]);
                a[mt][2] = __float_as_uint(As[(kc + 4) * 136 + row]);
                a[mt][3] = __float_as_uint(As[(kc + 4) * 136 + row + 8]);
            }
            #pragma unroll
            for (int nt = 0; nt < 4; ++nt) {
                const int colB = wn + nt * 8 + gr;
                bf[nt][0] = __float_as_uint(Bs[kc * 136 + colB]);
                bf[nt][1] = __float_as_uint(Bs[(kc + 4) * 136 + colB]);
            }
            #pragma unroll
            for (int mt = 0; mt < 4; ++mt)
                #pragma unroll
                for (int nt = 0; nt < 4; ++nt)
                    asm volatile(
                        "mma.sync.aligned.m16n8k8.row.col.f32.tf32.tf32.f32 "
                        "{%0,%1,%2,%3}, {%4,%5,%6,%7}, {%8,%9}, {%0,%1,%2,%3};\n"
                        : "+f"(acc[mt][nt][0]), "+f"(acc[mt][nt][1]),
                          "+f"(acc[mt][nt][2]), "+f"(acc[mt][nt][3])
                        : "r"(a[mt][0]), "r"(a[mt][1]),
                          "r"(a[mt][2]), "r"(a[mt][3]),
                          "r"(bf[nt][0]), "r"(bf[nt][1]));
        }
    };

    // ---- pipelined main loop ----
    int buf = 0;
    load_A(0, smem);
    if (CONV1) ldg_B1(0); else load_B2(0, smem + BK * 136);
    asm volatile("cp.async.commit_group;\n");

    for (int kt = 0; kt < KT; ++kt) {
        float* As = smem + buf * STAGEF;
        float* Bs = As + BK * 136;
        asm volatile("cp.async.wait_group 0;\n");
        if (CONV1) sts_B1(Bs);
        __syncthreads();
        if (kt + 1 < KT) {
            float* As1 = smem + (buf ^ 1) * STAGEF;
            load_A(kt + 1, As1);
            if (CONV1) ldg_B1(kt + 1); else load_B2(kt + 1, As1 + BK * 136);
            asm volatile("cp.async.commit_group;\n");
        }
        compute(As, Bs);
        buf ^= 1;
    }

    // ---- epilogue ----
    float* dst = CONV1 ? (g_y + b * CMID * HW) : (outp + b * COUT * HW);
    const int gr = lane >> 2;
    const int gc = (lane & 3) * 2;
    #pragma unroll
    for (int mt = 0; mt < 4; ++mt) {
        #pragma unroll
        for (int nt = 0; nt < 4; ++nt) {
            #pragma unroll
            for (int c = 0; c < 4; ++c) {
                const int row = m0 + wm + mt * 16 + gr + ((c >= 2) ? 8 : 0);
                const int col = n0 + wn + nt * 8 + gc + (c & 1);
                if (col < HW) {
                    float v = acc[mt][nt][c];
                    if (CONV1)
                        dst[row * HW + col] =
                            __uint_as_float(f2tf32(fmaxf(v, 0.f)));
                    else
                        dst[row * HW + col] = v + bias[row];
                }
            }
        }
    }
}

extern "C" void kernel_launch(void* const* d_in, const int* in_sizes, int n_in,
                              void* d_out, int out_size) {
    (void)in_sizes; (void)n_in; (void)out_size;
    const float* x  = (const float*)d_in[0];
    const float* bw = (const float*)d_in[1];   // binary_w [512,256,3,3]
    const float* fw = (const float*)d_in[2];   // fc_w [256,512,1,1]
    const float* fb = (const float*)d_in[3];   // fc_b [256]
    float* out = (float*)d_out;

    const int smem_bytes = 2 * STAGEF * 4;   // 69632
    cudaFuncSetAttribute(gemm_kernel<true>,
                         cudaFuncAttributeMaxDynamicSharedMemorySize, smem_bytes);
    cudaFuncSetAttribute(gemm_kernel<false>,
                         cudaFuncAttributeMaxDynamicSharedMemorySize, smem_bytes);

    prep_wA<<<(KCONV * CMID + 255) / 256, 256>>>(bw);
    prep_wB<<<(CMID * COUT + 255) / 256, 256>>>(fw);
    prep_x <<<(BATCH * CIN * HW + 255) / 256, 256>>>(x);

    // conv1 + relu -> g_y : M=512 (4 tiles), N=3136 (25 tiles of 128), 32 batches
    gemm_kernel<true ><<<dim3(25, 4, 32), 256, smem_bytes>>>(nullptr, nullptr);
    // 1x1 conv + bias -> out : M=256 (2 tiles)
    gemm_kernel<false><<<dim3(25, 2, 32), 256, smem_bytes>>>(fb, out);
}